// round 7
// baseline (speedup 1.0000x reference)
// Round 7: MLP 2-samples-per-weight-load (fma-bound); FPS redux.sync + 4-slot atomic spread.
#include <cuda_runtime.h>

#define NB 8
#define NN 8192
#define NS 2048

typedef unsigned long long u64;

#define PK2(d, lo, hi)   asm("mov.b64 %0, {%1,%2};" : "=l"(d) : "f"(lo), "f"(hi))
#define UPK2(lo, hi, v)  asm("mov.b64 {%0,%1}, %2;" : "=f"(lo), "=f"(hi) : "l"(v))
#define ADD2(d, a, b)    asm("add.rn.f32x2 %0, %1, %2;" : "=l"(d) : "l"(a), "l"(b))
#define MUL2(d, a, b)    asm("mul.rn.f32x2 %0, %1, %2;" : "=l"(d) : "l"(a), "l"(b))
#define FMA2(d, a, b, c) asm("fma.rn.f32x2 %0, %1, %2, %3;" : "=l"(d) : "l"(a), "l"(b), "l"(c))

// folded weights: w0t[9*64]@0 b0@576 w1t[64*64]@640 b1@4736 w2t[64*128]@4800 b2@12992
__device__ __align__(16) float g_w[13120];
__device__ int g_ball[NB * NS * 32];

__global__ void prep_kernel(const float* w0, const float* b0, const float* g0, const float* bt0, const float* m0, const float* v0,
                            const float* w1, const float* b1, const float* g1, const float* bt1, const float* m1, const float* v1,
                            const float* w2, const float* b2, const float* g2, const float* bt2, const float* m2, const float* v2) {
    int t = threadIdx.x;
    if (t < 64) {
        float s = g0[t] * rsqrtf(v0[t] + 1e-5f);
        for (int c = 0; c < 9; c++) g_w[c * 64 + t] = w0[t * 9 + c] * s;
        g_w[576 + t] = (b0[t] - m0[t]) * s + bt0[t];
        float s1 = g1[t] * rsqrtf(v1[t] + 1e-5f);
        for (int c = 0; c < 64; c++) g_w[640 + c * 64 + t] = w1[t * 64 + c] * s1;
        g_w[4736 + t] = (b1[t] - m1[t]) * s1 + bt1[t];
    }
    if (t < 128) {
        float s2 = g2[t] * rsqrtf(v2[t] + 1e-5f);
        for (int c = 0; c < 64; c++) g_w[4800 + c * 128 + t] = w2[t * 64 + c] * s2;
        g_w[12992 + t] = (b2[t] - m2[t]) * s2 + bt2[t];
    }
}

__global__ __launch_bounds__(1024, 1) void fps_kernel(const float* __restrict__ xyz, float* __restrict__ nxyz) {
    extern __shared__ float sx[];            // 24576 floats
    __shared__ u64 slot[4][4];               // [iter&3][warp&3]
    int b = blockIdx.x, t = threadIdx.x;
    int warp4 = (t >> 5) & 3;
    if (t < 16) slot[t >> 2][t & 3] = 0ull;
    const float4* src = (const float4*)(xyz + (size_t)b * NN * 3);
    float4* d4 = (float4*)sx;
    for (int i = t; i < 6144; i += 1024) d4[i] = src[i];
    __syncthreads();
    // pair j holds points p0 = t + (2j)*1024 (lo) and p1 = p0 + 1024 (hi)
    u64 px2[4], py2[4], pz2[4];
    float dd[8];
#pragma unroll
    for (int j = 0; j < 4; j++) {
        int p0 = t + ((2 * j) << 10), p1 = p0 + 1024;
        PK2(px2[j], sx[p0 * 3 + 0], sx[p1 * 3 + 0]);
        PK2(py2[j], sx[p0 * 3 + 1], sx[p1 * 3 + 1]);
        PK2(pz2[j], sx[p0 * 3 + 2], sx[p1 * 3 + 2]);
        dd[2 * j] = 1e10f; dd[2 * j + 1] = 1e10f;
    }
    int far = 0;
    float* ob = nxyz + (size_t)b * NS * 3;
    for (int it = 0; it < NS; it++) {
        float cx = sx[far * 3], cy = sx[far * 3 + 1], cz = sx[far * 3 + 2];
        if (t == 0) { ob[it * 3] = cx; ob[it * 3 + 1] = cy; ob[it * 3 + 2] = cz; }
        if (t >= 32 && t < 36) slot[(it + 2) & 3][t - 32] = 0ull;   // reset 2 iters ahead (barrier-separated)
        float ncx = -cx, ncy = -cy, ncz = -cz;
        u64 ncx2, ncy2, ncz2;
        PK2(ncx2, ncx, ncx); PK2(ncy2, ncy, ncy); PK2(ncz2, ncz, ncz);
        float m01 = -1.f, m23 = -1.f;
#pragma unroll
        for (int j = 0; j < 4; j++) {
            u64 dx, dy, dz, xx, yy, zz, s01;
            ADD2(dx, px2[j], ncx2);        // px - cx (exact: a + (-b) == a - b)
            ADD2(dy, py2[j], ncy2);
            ADD2(dz, pz2[j], ncz2);
            MUL2(xx, dx, dx);
            MUL2(yy, dy, dy);
            MUL2(zz, dz, dz);
            ADD2(s01, xx, yy);
            ADD2(s01, s01, zz);            // (x2+y2)+z2, same association as before
            float s0, s1;
            UPK2(s0, s1, s01);
            dd[2 * j]     = fminf(dd[2 * j], s0);
            dd[2 * j + 1] = fminf(dd[2 * j + 1], s1);
            float mj = fmaxf(dd[2 * j], dd[2 * j + 1]);
            if (j < 2) m01 = fmaxf(m01, mj); else m23 = fmaxf(m23, mj);
        }
        float mymax = fmaxf(m01, m23);
        unsigned mb = __float_as_uint(mymax);          // nonneg floats: bit order == value order
        unsigned wmax = __reduce_max_sync(~0u, mb);
        if (mb == wmax) {
            int p = 0;
#pragma unroll
            for (int k = 7; k >= 0; k--)
                if (dd[k] == mymax) p = t + (k << 10); // descending k keeps smallest index
            u64 pk = ((u64)mb << 32) | (u64)(~(unsigned)p);
            atomicMax(&slot[it & 3][warp4], pk);
        }
        __syncthreads();
        u64 s0 = slot[it & 3][0], s1 = slot[it & 3][1];
        u64 s2 = slot[it & 3][2], s3 = slot[it & 3][3];
        u64 sm = s0 > s1 ? s0 : s1;
        u64 sn = s2 > s3 ? s2 : s3;
        sm = sm > sn ? sm : sn;
        far = (int)(~(unsigned)sm);
    }
}

__global__ __launch_bounds__(256) void ball_kernel(const float* __restrict__ xyz, const float* __restrict__ nxyz) {
    __shared__ float tile[6144];
    int b = blockIdx.x >> 8;
    int s = ((blockIdx.x & 255) << 3) + (threadIdx.x >> 5);
    int lane = threadIdx.x & 31;
    const float* nx = nxyz + (size_t)(b * NS + s) * 3;
    float cx = nx[0], cy = nx[1], cz = nx[2];
    float sn = cx * cx + cy * cy + cz * cz;
    const float R2 = 0.0625f, BIG = 1e30f;
    float kd = BIG; int ki = 0;
    float thr = BIG;
    for (int n0 = 0; n0 < NN; n0 += 2048) {
        __syncthreads();
        const float4* src = (const float4*)(xyz + (size_t)b * NN * 3 + n0 * 3);
        float4* d4 = (float4*)tile;
        for (int i = threadIdx.x; i < 1536; i += 256) d4[i] = src[i];
        __syncthreads();
        for (int c = 0; c < 2048; c += 32) {
            int p = c + lane;
            float x = tile[p * 3], y = tile[p * 3 + 1], z = tile[p * 3 + 2];
            float sp = x * x + y * y + z * z;
            float dot = x * cx + y * cy + z * cz;
            float d2 = sn + sp - 2.f * dot;
            unsigned m = __ballot_sync(~0u, d2 <= R2 && d2 < thr);
            while (m) {
                int sl = __ffs(m) - 1; m &= m - 1;
                float dv = __shfl_sync(~0u, d2, sl);
                if (dv < thr) {
                    float mv = kd; int mi = ki, ml = lane;
#pragma unroll
                    for (int o = 16; o; o >>= 1) {
                        float ov = __shfl_xor_sync(~0u, mv, o);
                        int oi = __shfl_xor_sync(~0u, mi, o);
                        int ol = __shfl_xor_sync(~0u, ml, o);
                        if (ov > mv || (ov == mv && (oi > mi || (oi == mi && ol > ml)))) { mv = ov; mi = oi; ml = ol; }
                    }
                    if (lane == ml) { kd = dv; ki = n0 + c + sl; }
                    float tv = kd;
#pragma unroll
                    for (int o = 16; o; o >>= 1) tv = fmaxf(tv, __shfl_xor_sync(~0u, tv, o));
                    thr = tv;
                }
            }
        }
    }
    float nv = kd; int ni = ki;
#pragma unroll
    for (int o = 16; o; o >>= 1) {
        float ov = __shfl_xor_sync(~0u, nv, o);
        int oi = __shfl_xor_sync(~0u, ni, o);
        if (ov < nv || (ov == nv && oi < ni)) { nv = ov; ni = oi; }
    }
    g_ball[((b * NS + s) << 5) + lane] = (kd >= BIG) ? ni : ki;
}

// SMEM: W[8448] | A0[2 pairs][64ch][64] | A1[same] = 24832 floats = 99328 B
// warp = (pair g = warp&1, cout-quarter h = warp>>1); lane = neighbor point.
// Each warp processes 2 samples per weight load. Activation layout [ch][lane*2+samp].
__global__ __launch_bounds__(256, 2) void mlp_kernel(const float* __restrict__ xyz, const float* __restrict__ pts,
                                                     const float* __restrict__ nxyz, float* __restrict__ outp) {
    extern __shared__ float S[];
    float* W  = S;
    float* A0 = S + 8448;
    float* A1 = S + 16640;
    int tid = threadIdx.x;
    int warp = tid >> 5, lane = tid & 31;
    int g = warp & 1, h = warp >> 1;
    int base = blockIdx.x * 4;
    int gsA = base + 2 * g, gsB = gsA + 1;   // two global sample indices for this warp
    {   // phase A: w0t,b0,w1t,b1 = 4800 floats
        const float4* g4 = (const float4*)g_w;
        float4* w4 = (float4*)W;
        for (int i = tid; i < 1200; i += 256) w4[i] = g4[i];
    }
    int bb = gsA >> 11;
    float fA[9], fB[9];
    {
        int gi = g_ball[(gsA << 5) + lane];
        const float* nx = nxyz + (size_t)gsA * 3;
        const float* P = xyz + (size_t)(bb * NN + gi) * 3;
        const float2* Q = (const float2*)(pts + (size_t)(bb * NN + gi) * 6);
        fA[0] = P[0] - nx[0]; fA[1] = P[1] - nx[1]; fA[2] = P[2] - nx[2];
        float2 q0 = Q[0], q1 = Q[1], q2 = Q[2];
        fA[3] = q0.x; fA[4] = q0.y; fA[5] = q1.x; fA[6] = q1.y; fA[7] = q2.x; fA[8] = q2.y;
    }
    {
        int gi = g_ball[(gsB << 5) + lane];
        const float* nx = nxyz + (size_t)gsB * 3;
        const float* P = xyz + (size_t)(bb * NN + gi) * 3;
        const float2* Q = (const float2*)(pts + (size_t)(bb * NN + gi) * 6);
        fB[0] = P[0] - nx[0]; fB[1] = P[1] - nx[1]; fB[2] = P[2] - nx[2];
        float2 q0 = Q[0], q1 = Q[1], q2 = Q[2];
        fB[3] = q0.x; fB[4] = q0.y; fB[5] = q1.x; fB[6] = q1.y; fB[7] = q2.x; fB[8] = q2.y;
    }
    __syncthreads();

    float* P0 = A0 + g * 4096;   // [64ch][64]: ch*64 + 2*lane + samp
    float* P1 = A1 + g * 4096;
    u64 acc[16];                 // acc[0..7] sample A (couts h*16+2q,+1), acc[8..15] sample B
    {   // layer1 9->64: couts [h*16, h*16+16)
        const u64* bp = (const u64*)(W + 576 + h * 16);
#pragma unroll
        for (int q = 0; q < 8; q++) { acc[q] = bp[q]; acc[8 + q] = bp[q]; }
#pragma unroll
        for (int c = 0; c < 9; c++) {
            u64 xa, xb; PK2(xa, fA[c], fA[c]); PK2(xb, fB[c], fB[c]);
            const ulonglong2* wr = (const ulonglong2*)(W + c * 64 + h * 16);
#pragma unroll
            for (int q = 0; q < 4; q++) {
                ulonglong2 w = wr[q];
                FMA2(acc[2 * q], xa, w.x, acc[2 * q]);
                FMA2(acc[2 * q + 1], xa, w.y, acc[2 * q + 1]);
                FMA2(acc[8 + 2 * q], xb, w.x, acc[8 + 2 * q]);
                FMA2(acc[9 + 2 * q], xb, w.y, acc[9 + 2 * q]);
            }
        }
#pragma unroll
        for (int q = 0; q < 8; q++) {
            float r0, r1, r2, r3;
            UPK2(r0, r1, acc[q]); UPK2(r2, r3, acc[8 + q]);
            int c0 = h * 16 + 2 * q;
            P0[c0 * 64 + 2 * lane]       = fmaxf(r0, 0.f);
            P0[(c0 + 1) * 64 + 2 * lane] = fmaxf(r1, 0.f);
            P0[c0 * 64 + 2 * lane + 1]       = fmaxf(r2, 0.f);
            P0[(c0 + 1) * 64 + 2 * lane + 1] = fmaxf(r3, 0.f);
        }
    }
    __syncthreads();
    {   // layer2 64->64
        const u64* bp = (const u64*)(W + 4736 + h * 16);
#pragma unroll
        for (int q = 0; q < 8; q++) { acc[q] = bp[q]; acc[8 + q] = bp[q]; }
#pragma unroll 8
        for (int c = 0; c < 64; c++) {
            float2 xv = *(const float2*)(P0 + c * 64 + 2 * lane);
            u64 xa, xb; PK2(xa, xv.x, xv.x); PK2(xb, xv.y, xv.y);
            const ulonglong2* wr = (const ulonglong2*)(W + 640 + c * 64 + h * 16);
#pragma unroll
            for (int q = 0; q < 4; q++) {
                ulonglong2 w = wr[q];
                FMA2(acc[2 * q], xa, w.x, acc[2 * q]);
                FMA2(acc[2 * q + 1], xa, w.y, acc[2 * q + 1]);
                FMA2(acc[8 + 2 * q], xb, w.x, acc[8 + 2 * q]);
                FMA2(acc[9 + 2 * q], xb, w.y, acc[9 + 2 * q]);
            }
        }
#pragma unroll
        for (int q = 0; q < 8; q++) {
            float r0, r1, r2, r3;
            UPK2(r0, r1, acc[q]); UPK2(r2, r3, acc[8 + q]);
            int c0 = h * 16 + 2 * q;
            P1[c0 * 64 + 2 * lane]       = fmaxf(r0, 0.f);
            P1[(c0 + 1) * 64 + 2 * lane] = fmaxf(r1, 0.f);
            P1[c0 * 64 + 2 * lane + 1]       = fmaxf(r2, 0.f);
            P1[(c0 + 1) * 64 + 2 * lane + 1] = fmaxf(r3, 0.f);
        }
    }
    __syncthreads();
    {   // phase B weights: w2t,b2 = 8320 floats
        const float4* g4 = (const float4*)(g_w + 4800);
        float4* w4 = (float4*)W;
        for (int i = tid; i < 2080; i += 256) w4[i] = g4[i];
    }
    __syncthreads();
#pragma unroll 1
    for (int sub = 0; sub < 2; sub++) {  // layer3 64->128: this warp covers couts [h*32, h*32+32) in 2 subs of 16
        int cb = h * 32 + sub * 16;
        const u64* bp = (const u64*)(W + 8192 + cb);
#pragma unroll
        for (int q = 0; q < 8; q++) { acc[q] = bp[q]; acc[8 + q] = bp[q]; }
#pragma unroll 8
        for (int c = 0; c < 64; c++) {
            float2 xv = *(const float2*)(P1 + c * 64 + 2 * lane);
            u64 xa, xb; PK2(xa, xv.x, xv.x); PK2(xb, xv.y, xv.y);
            const ulonglong2* wr = (const ulonglong2*)(W + c * 128 + cb);
#pragma unroll
            for (int q = 0; q < 4; q++) {
                ulonglong2 w = wr[q];
                FMA2(acc[2 * q], xa, w.x, acc[2 * q]);
                FMA2(acc[2 * q + 1], xa, w.y, acc[2 * q + 1]);
                FMA2(acc[8 + 2 * q], xb, w.x, acc[8 + 2 * q]);
                FMA2(acc[9 + 2 * q], xb, w.y, acc[9 + 2 * q]);
            }
        }
        // maxpool: 32 virtual couts = [sampleA couts 0..15, sampleB couts 0..15]
        float v[32];
#pragma unroll
        for (int q = 0; q < 8; q++) {
            UPK2(v[2 * q], v[2 * q + 1], acc[q]);
            UPK2(v[16 + 2 * q], v[17 + 2 * q], acc[8 + q]);
        }
#pragma unroll
        for (int o = 16; o; o >>= 1) {
#pragma unroll
            for (int j = 0; j < o; j++) {
                float xj   = (lane & o) ? v[j] : v[j + o];
                float r    = __shfl_xor_sync(~0u, xj, o);
                float mine = (lane & o) ? v[j + o] : v[j];
                v[j] = fmaxf(mine, r);
            }
        }
        if (lane < 16) outp[(size_t)gsA * 128 + cb + lane] = fmaxf(v[0], 0.f);
        else           outp[(size_t)gsB * 128 + cb + (lane - 16)] = fmaxf(v[0], 0.f);
    }
}

extern "C" void kernel_launch(void* const* d_in, const int* in_sizes, int n_in,
                              void* d_out, int out_size) {
    const float* xyz = (const float*)d_in[0];
    const float* pts = (const float*)d_in[1];
    float* out = (float*)d_out;
    float* nxyz = out;                       // (B,S,3)
    float* npts = out + NB * NS * 3;         // (B,S,128)
    cudaFuncSetAttribute(fps_kernel, cudaFuncAttributeMaxDynamicSharedMemorySize, 98304);
    cudaFuncSetAttribute(mlp_kernel, cudaFuncAttributeMaxDynamicSharedMemorySize, 99328);
    prep_kernel<<<1, 128>>>((const float*)d_in[2], (const float*)d_in[3], (const float*)d_in[4],
                            (const float*)d_in[5], (const float*)d_in[6], (const float*)d_in[7],
                            (const float*)d_in[8], (const float*)d_in[9], (const float*)d_in[10],
                            (const float*)d_in[11], (const float*)d_in[12], (const float*)d_in[13],
                            (const float*)d_in[14], (const float*)d_in[15], (const float*)d_in[16],
                            (const float*)d_in[17], (const float*)d_in[18], (const float*)d_in[19]);
    fps_kernel<<<NB, 1024, 98304>>>(xyz, nxyz);
    ball_kernel<<<NB * 256, 256>>>(xyz, nxyz);
    mlp_kernel<<<NB * NS / 4, 256, 99328>>>(xyz, pts, nxyz, npts);
}

// round 9
// speedup vs baseline: 1.1659x; 1.1659x over previous
// Round 9: FPS atomic-free REDUX two-level argmax (1 barrier, 32-bit only); MLP/ball from round 7.
#include <cuda_runtime.h>

#define NB 8
#define NN 8192
#define NS 2048

typedef unsigned long long u64;

#define PK2(d, lo, hi)   asm("mov.b64 %0, {%1,%2};" : "=l"(d) : "f"(lo), "f"(hi))
#define UPK2(lo, hi, v)  asm("mov.b64 {%0,%1}, %2;" : "=f"(lo), "=f"(hi) : "l"(v))
#define ADD2(d, a, b)    asm("add.rn.f32x2 %0, %1, %2;" : "=l"(d) : "l"(a), "l"(b))
#define MUL2(d, a, b)    asm("mul.rn.f32x2 %0, %1, %2;" : "=l"(d) : "l"(a), "l"(b))
#define FMA2(d, a, b, c) asm("fma.rn.f32x2 %0, %1, %2, %3;" : "=l"(d) : "l"(a), "l"(b), "l"(c))

// folded weights: w0t[9*64]@0 b0@576 w1t[64*64]@640 b1@4736 w2t[64*128]@4800 b2@12992
__device__ __align__(16) float g_w[13120];
__device__ int g_ball[NB * NS * 32];

__global__ void prep_kernel(const float* w0, const float* b0, const float* g0, const float* bt0, const float* m0, const float* v0,
                            const float* w1, const float* b1, const float* g1, const float* bt1, const float* m1, const float* v1,
                            const float* w2, const float* b2, const float* g2, const float* bt2, const float* m2, const float* v2) {
    int t = threadIdx.x;
    if (t < 64) {
        float s = g0[t] * rsqrtf(v0[t] + 1e-5f);
        for (int c = 0; c < 9; c++) g_w[c * 64 + t] = w0[t * 9 + c] * s;
        g_w[576 + t] = (b0[t] - m0[t]) * s + bt0[t];
        float s1 = g1[t] * rsqrtf(v1[t] + 1e-5f);
        for (int c = 0; c < 64; c++) g_w[640 + c * 64 + t] = w1[t * 64 + c] * s1;
        g_w[4736 + t] = (b1[t] - m1[t]) * s1 + bt1[t];
    }
    if (t < 128) {
        float s2 = g2[t] * rsqrtf(v2[t] + 1e-5f);
        for (int c = 0; c < 64; c++) g_w[4800 + c * 128 + t] = w2[t * 64 + c] * s2;
        g_w[12992 + t] = (b2[t] - m2[t]) * s2 + bt2[t];
    }
}

__global__ __launch_bounds__(1024, 1) void fps_kernel(const float* __restrict__ xyz, float* __restrict__ nxyz) {
    extern __shared__ float sx[];            // 24576 floats
    __shared__ unsigned sval[2][32];         // [iter&1][warp] winner value bits
    __shared__ int      sidx[2][32];         // [iter&1][warp] winner index
    int b = blockIdx.x, t = threadIdx.x;
    int warp = t >> 5, lane = t & 31;
    const float4* src = (const float4*)(xyz + (size_t)b * NN * 3);
    float4* d4 = (float4*)sx;
    for (int i = t; i < 6144; i += 1024) d4[i] = src[i];
    __syncthreads();
    // pair j holds points p0 = t + (2j)*1024 (lo) and p1 = p0 + 1024 (hi)
    u64 px2[4], py2[4], pz2[4];
    float dd[8];
#pragma unroll
    for (int j = 0; j < 4; j++) {
        int p0 = t + ((2 * j) << 10), p1 = p0 + 1024;
        PK2(px2[j], sx[p0 * 3 + 0], sx[p1 * 3 + 0]);
        PK2(py2[j], sx[p0 * 3 + 1], sx[p1 * 3 + 1]);
        PK2(pz2[j], sx[p0 * 3 + 2], sx[p1 * 3 + 2]);
        dd[2 * j] = 1e10f; dd[2 * j + 1] = 1e10f;
    }
    int far = 0;
    float* ob = nxyz + (size_t)b * NS * 3;
    for (int it = 0; it < NS; it++) {
        float cx = sx[far * 3], cy = sx[far * 3 + 1], cz = sx[far * 3 + 2];
        if (t == 0) { ob[it * 3] = cx; ob[it * 3 + 1] = cy; ob[it * 3 + 2] = cz; }
        float ncx = -cx, ncy = -cy, ncz = -cz;
        u64 ncx2, ncy2, ncz2;
        PK2(ncx2, ncx, ncx); PK2(ncy2, ncy, ncy); PK2(ncz2, ncz, ncz);
        float m01 = -1.f, m23 = -1.f;
#pragma unroll
        for (int j = 0; j < 4; j++) {
            u64 dx, dy, dz, xx, yy, zz, s01;
            ADD2(dx, px2[j], ncx2);        // px - cx (exact: a + (-b) == a - b)
            ADD2(dy, py2[j], ncy2);
            ADD2(dz, pz2[j], ncz2);
            MUL2(xx, dx, dx);
            MUL2(yy, dy, dy);
            MUL2(zz, dz, dz);
            ADD2(s01, xx, yy);
            ADD2(s01, s01, zz);            // (x2+y2)+z2, same association as before
            float s0, s1;
            UPK2(s0, s1, s01);
            dd[2 * j]     = fminf(dd[2 * j], s0);
            dd[2 * j + 1] = fminf(dd[2 * j + 1], s1);
            float mj = fmaxf(dd[2 * j], dd[2 * j + 1]);
            if (j < 2) m01 = fmaxf(m01, mj); else m23 = fmaxf(m23, mj);
        }
        float mymax = fmaxf(m01, m23);
        unsigned mb = __float_as_uint(mymax);          // nonneg floats: bit order == value order
        unsigned wmax = __reduce_max_sync(~0u, mb);
        unsigned p = 0x7fffffffu;
        if (mb == wmax) {
#pragma unroll
            for (int k = 7; k >= 0; k--)
                if (dd[k] == mymax) p = (unsigned)(t + (k << 10)); // descending k keeps smallest index
        }
        unsigned pw = __reduce_min_sync(~0u, p);
        if (lane == 0) { sval[it & 1][warp] = wmax; sidx[it & 1][warp] = (int)pw; }
        __syncthreads();
        // every warp reduces the same 32 (value, index) pairs; no atomics, no 2nd barrier
        unsigned v = sval[it & 1][lane];
        unsigned bm = __reduce_max_sync(~0u, v);
        unsigned cand = (v == bm) ? (unsigned)sidx[it & 1][lane] : 0x7fffffffu;
        far = (int)__reduce_min_sync(~0u, cand);
    }
}

__global__ __launch_bounds__(256) void ball_kernel(const float* __restrict__ xyz, const float* __restrict__ nxyz) {
    __shared__ float tile[6144];
    int b = blockIdx.x >> 8;
    int s = ((blockIdx.x & 255) << 3) + (threadIdx.x >> 5);
    int lane = threadIdx.x & 31;
    const float* nx = nxyz + (size_t)(b * NS + s) * 3;
    float cx = nx[0], cy = nx[1], cz = nx[2];
    float sn = cx * cx + cy * cy + cz * cz;
    const float R2 = 0.0625f, BIG = 1e30f;
    float kd = BIG; int ki = 0;
    float thr = BIG;
    for (int n0 = 0; n0 < NN; n0 += 2048) {
        __syncthreads();
        const float4* src = (const float4*)(xyz + (size_t)b * NN * 3 + n0 * 3);
        float4* d4 = (float4*)tile;
        for (int i = threadIdx.x; i < 1536; i += 256) d4[i] = src[i];
        __syncthreads();
        for (int c = 0; c < 2048; c += 32) {
            int p = c + lane;
            float x = tile[p * 3], y = tile[p * 3 + 1], z = tile[p * 3 + 2];
            float sp = x * x + y * y + z * z;
            float dot = x * cx + y * cy + z * cz;
            float d2 = sn + sp - 2.f * dot;
            unsigned m = __ballot_sync(~0u, d2 <= R2 && d2 < thr);
            while (m) {
                int sl = __ffs(m) - 1; m &= m - 1;
                float dv = __shfl_sync(~0u, d2, sl);
                if (dv < thr) {
                    float mv = kd; int mi = ki, ml = lane;
#pragma unroll
                    for (int o = 16; o; o >>= 1) {
                        float ov = __shfl_xor_sync(~0u, mv, o);
                        int oi = __shfl_xor_sync(~0u, mi, o);
                        int ol = __shfl_xor_sync(~0u, ml, o);
                        if (ov > mv || (ov == mv && (oi > mi || (oi == mi && ol > ml)))) { mv = ov; mi = oi; ml = ol; }
                    }
                    if (lane == ml) { kd = dv; ki = n0 + c + sl; }
                    float tv = kd;
#pragma unroll
                    for (int o = 16; o; o >>= 1) tv = fmaxf(tv, __shfl_xor_sync(~0u, tv, o));
                    thr = tv;
                }
            }
        }
    }
    float nv = kd; int ni = ki;
#pragma unroll
    for (int o = 16; o; o >>= 1) {
        float ov = __shfl_xor_sync(~0u, nv, o);
        int oi = __shfl_xor_sync(~0u, ni, o);
        if (ov < nv || (ov == nv && oi < ni)) { nv = ov; ni = oi; }
    }
    g_ball[((b * NS + s) << 5) + lane] = (kd >= BIG) ? ni : ki;
}

// SMEM: W[8448] | A0[2 pairs][64ch][64] | A1[same] = 24832 floats = 99328 B
// warp = (pair g = warp&1, cout-quarter h = warp>>1); lane = neighbor point.
// Each warp processes 2 samples per weight load. Activation layout [ch][lane*2+samp].
__global__ __launch_bounds__(256, 2) void mlp_kernel(const float* __restrict__ xyz, const float* __restrict__ pts,
                                                     const float* __restrict__ nxyz, float* __restrict__ outp) {
    extern __shared__ float S[];
    float* W  = S;
    float* A0 = S + 8448;
    float* A1 = S + 16640;
    int tid = threadIdx.x;
    int warp = tid >> 5, lane = tid & 31;
    int g = warp & 1, h = warp >> 1;
    int base = blockIdx.x * 4;
    int gsA = base + 2 * g, gsB = gsA + 1;   // two global sample indices for this warp
    {   // phase A: w0t,b0,w1t,b1 = 4800 floats
        const float4* g4 = (const float4*)g_w;
        float4* w4 = (float4*)W;
        for (int i = tid; i < 1200; i += 256) w4[i] = g4[i];
    }
    int bb = gsA >> 11;
    float fA[9], fB[9];
    {
        int gi = g_ball[(gsA << 5) + lane];
        const float* nx = nxyz + (size_t)gsA * 3;
        const float* P = xyz + (size_t)(bb * NN + gi) * 3;
        const float2* Q = (const float2*)(pts + (size_t)(bb * NN + gi) * 6);
        fA[0] = P[0] - nx[0]; fA[1] = P[1] - nx[1]; fA[2] = P[2] - nx[2];
        float2 q0 = Q[0], q1 = Q[1], q2 = Q[2];
        fA[3] = q0.x; fA[4] = q0.y; fA[5] = q1.x; fA[6] = q1.y; fA[7] = q2.x; fA[8] = q2.y;
    }
    {
        int gi = g_ball[(gsB << 5) + lane];
        const float* nx = nxyz + (size_t)gsB * 3;
        const float* P = xyz + (size_t)(bb * NN + gi) * 3;
        const float2* Q = (const float2*)(pts + (size_t)(bb * NN + gi) * 6);
        fB[0] = P[0] - nx[0]; fB[1] = P[1] - nx[1]; fB[2] = P[2] - nx[2];
        float2 q0 = Q[0], q1 = Q[1], q2 = Q[2];
        fB[3] = q0.x; fB[4] = q0.y; fB[5] = q1.x; fB[6] = q1.y; fB[7] = q2.x; fB[8] = q2.y;
    }
    __syncthreads();

    float* P0 = A0 + g * 4096;   // [64ch][64]: ch*64 + 2*lane + samp
    float* P1 = A1 + g * 4096;
    u64 acc[16];                 // acc[0..7] sample A (couts h*16+2q,+1), acc[8..15] sample B
    {   // layer1 9->64: couts [h*16, h*16+16)
        const u64* bp = (const u64*)(W + 576 + h * 16);
#pragma unroll
        for (int q = 0; q < 8; q++) { acc[q] = bp[q]; acc[8 + q] = bp[q]; }
#pragma unroll
        for (int c = 0; c < 9; c++) {
            u64 xa, xb; PK2(xa, fA[c], fA[c]); PK2(xb, fB[c], fB[c]);
            const ulonglong2* wr = (const ulonglong2*)(W + c * 64 + h * 16);
#pragma unroll
            for (int q = 0; q < 4; q++) {
                ulonglong2 w = wr[q];
                FMA2(acc[2 * q], xa, w.x, acc[2 * q]);
                FMA2(acc[2 * q + 1], xa, w.y, acc[2 * q + 1]);
                FMA2(acc[8 + 2 * q], xb, w.x, acc[8 + 2 * q]);
                FMA2(acc[9 + 2 * q], xb, w.y, acc[9 + 2 * q]);
            }
        }
#pragma unroll
        for (int q = 0; q < 8; q++) {
            float r0, r1, r2, r3;
            UPK2(r0, r1, acc[q]); UPK2(r2, r3, acc[8 + q]);
            int c0 = h * 16 + 2 * q;
            P0[c0 * 64 + 2 * lane]       = fmaxf(r0, 0.f);
            P0[(c0 + 1) * 64 + 2 * lane] = fmaxf(r1, 0.f);
            P0[c0 * 64 + 2 * lane + 1]       = fmaxf(r2, 0.f);
            P0[(c0 + 1) * 64 + 2 * lane + 1] = fmaxf(r3, 0.f);
        }
    }
    __syncthreads();
    {   // layer2 64->64
        const u64* bp = (const u64*)(W + 4736 + h * 16);
#pragma unroll
        for (int q = 0; q < 8; q++) { acc[q] = bp[q]; acc[8 + q] = bp[q]; }
#pragma unroll 8
        for (int c = 0; c < 64; c++) {
            float2 xv = *(const float2*)(P0 + c * 64 + 2 * lane);
            u64 xa, xb; PK2(xa, xv.x, xv.x); PK2(xb, xv.y, xv.y);
            const ulonglong2* wr = (const ulonglong2*)(W + 640 + c * 64 + h * 16);
#pragma unroll
            for (int q = 0; q < 4; q++) {
                ulonglong2 w = wr[q];
                FMA2(acc[2 * q], xa, w.x, acc[2 * q]);
                FMA2(acc[2 * q + 1], xa, w.y, acc[2 * q + 1]);
                FMA2(acc[8 + 2 * q], xb, w.x, acc[8 + 2 * q]);
                FMA2(acc[9 + 2 * q], xb, w.y, acc[9 + 2 * q]);
            }
        }
#pragma unroll
        for (int q = 0; q < 8; q++) {
            float r0, r1, r2, r3;
            UPK2(r0, r1, acc[q]); UPK2(r2, r3, acc[8 + q]);
            int c0 = h * 16 + 2 * q;
            P1[c0 * 64 + 2 * lane]       = fmaxf(r0, 0.f);
            P1[(c0 + 1) * 64 + 2 * lane] = fmaxf(r1, 0.f);
            P1[c0 * 64 + 2 * lane + 1]       = fmaxf(r2, 0.f);
            P1[(c0 + 1) * 64 + 2 * lane + 1] = fmaxf(r3, 0.f);
        }
    }
    __syncthreads();
    {   // phase B weights: w2t,b2 = 8320 floats
        const float4* g4 = (const float4*)(g_w + 4800);
        float4* w4 = (float4*)W;
        for (int i = tid; i < 2080; i += 256) w4[i] = g4[i];
    }
    __syncthreads();
#pragma unroll 1
    for (int sub = 0; sub < 2; sub++) {  // layer3 64->128: this warp covers couts [h*32, h*32+32) in 2 subs of 16
        int cb = h * 32 + sub * 16;
        const u64* bp = (const u64*)(W + 8192 + cb);
#pragma unroll
        for (int q = 0; q < 8; q++) { acc[q] = bp[q]; acc[8 + q] = bp[q]; }
#pragma unroll 8
        for (int c = 0; c < 64; c++) {
            float2 xv = *(const float2*)(P1 + c * 64 + 2 * lane);
            u64 xa, xb; PK2(xa, xv.x, xv.x); PK2(xb, xv.y, xv.y);
            const ulonglong2* wr = (const ulonglong2*)(W + c * 128 + cb);
#pragma unroll
            for (int q = 0; q < 4; q++) {
                ulonglong2 w = wr[q];
                FMA2(acc[2 * q], xa, w.x, acc[2 * q]);
                FMA2(acc[2 * q + 1], xa, w.y, acc[2 * q + 1]);
                FMA2(acc[8 + 2 * q], xb, w.x, acc[8 + 2 * q]);
                FMA2(acc[9 + 2 * q], xb, w.y, acc[9 + 2 * q]);
            }
        }
        // maxpool: 32 virtual couts = [sampleA couts 0..15, sampleB couts 0..15]
        float v[32];
#pragma unroll
        for (int q = 0; q < 8; q++) {
            UPK2(v[2 * q], v[2 * q + 1], acc[q]);
            UPK2(v[16 + 2 * q], v[17 + 2 * q], acc[8 + q]);
        }
#pragma unroll
        for (int o = 16; o; o >>= 1) {
#pragma unroll
            for (int j = 0; j < o; j++) {
                float xj   = (lane & o) ? v[j] : v[j + o];
                float r    = __shfl_xor_sync(~0u, xj, o);
                float mine = (lane & o) ? v[j + o] : v[j];
                v[j] = fmaxf(mine, r);
            }
        }
        if (lane < 16) outp[(size_t)gsA * 128 + cb + lane] = fmaxf(v[0], 0.f);
        else           outp[(size_t)gsB * 128 + cb + (lane - 16)] = fmaxf(v[0], 0.f);
    }
}

extern "C" void kernel_launch(void* const* d_in, const int* in_sizes, int n_in,
                              void* d_out, int out_size) {
    const float* xyz = (const float*)d_in[0];
    const float* pts = (const float*)d_in[1];
    float* out = (float*)d_out;
    float* nxyz = out;                       // (B,S,3)
    float* npts = out + NB * NS * 3;         // (B,S,128)
    cudaFuncSetAttribute(fps_kernel, cudaFuncAttributeMaxDynamicSharedMemorySize, 98304);
    cudaFuncSetAttribute(mlp_kernel, cudaFuncAttributeMaxDynamicSharedMemorySize, 99328);
    prep_kernel<<<1, 128>>>((const float*)d_in[2], (const float*)d_in[3], (const float*)d_in[4],
                            (const float*)d_in[5], (const float*)d_in[6], (const float*)d_in[7],
                            (const float*)d_in[8], (const float*)d_in[9], (const float*)d_in[10],
                            (const float*)d_in[11], (const float*)d_in[12], (const float*)d_in[13],
                            (const float*)d_in[14], (const float*)d_in[15], (const float*)d_in[16],
                            (const float*)d_in[17], (const float*)d_in[18], (const float*)d_in[19]);
    fps_kernel<<<NB, 1024, 98304>>>(xyz, nxyz);
    ball_kernel<<<NB * 256, 256>>>(xyz, nxyz);
    mlp_kernel<<<NB * NS / 4, 256, 99328>>>(xyz, pts, nxyz, npts);
}

// round 10
// speedup vs baseline: 1.3895x; 1.1918x over previous
// Round 10: FPS 512thr x 16pts (halve overhead warps); ball REDUX eviction; MLP from r7.
#include <cuda_runtime.h>

#define NB 8
#define NN 8192
#define NS 2048

typedef unsigned long long u64;

#define PK2(d, lo, hi)   asm("mov.b64 %0, {%1,%2};" : "=l"(d) : "f"(lo), "f"(hi))
#define UPK2(lo, hi, v)  asm("mov.b64 {%0,%1}, %2;" : "=f"(lo), "=f"(hi) : "l"(v))
#define ADD2(d, a, b)    asm("add.rn.f32x2 %0, %1, %2;" : "=l"(d) : "l"(a), "l"(b))
#define MUL2(d, a, b)    asm("mul.rn.f32x2 %0, %1, %2;" : "=l"(d) : "l"(a), "l"(b))
#define FMA2(d, a, b, c) asm("fma.rn.f32x2 %0, %1, %2, %3;" : "=l"(d) : "l"(a), "l"(b), "l"(c))

// folded weights: w0t[9*64]@0 b0@576 w1t[64*64]@640 b1@4736 w2t[64*128]@4800 b2@12992
__device__ __align__(16) float g_w[13120];
__device__ int g_ball[NB * NS * 32];

__global__ void prep_kernel(const float* w0, const float* b0, const float* g0, const float* bt0, const float* m0, const float* v0,
                            const float* w1, const float* b1, const float* g1, const float* bt1, const float* m1, const float* v1,
                            const float* w2, const float* b2, const float* g2, const float* bt2, const float* m2, const float* v2) {
    int t = threadIdx.x;
    if (t < 64) {
        float s = g0[t] * rsqrtf(v0[t] + 1e-5f);
        for (int c = 0; c < 9; c++) g_w[c * 64 + t] = w0[t * 9 + c] * s;
        g_w[576 + t] = (b0[t] - m0[t]) * s + bt0[t];
        float s1 = g1[t] * rsqrtf(v1[t] + 1e-5f);
        for (int c = 0; c < 64; c++) g_w[640 + c * 64 + t] = w1[t * 64 + c] * s1;
        g_w[4736 + t] = (b1[t] - m1[t]) * s1 + bt1[t];
    }
    if (t < 128) {
        float s2 = g2[t] * rsqrtf(v2[t] + 1e-5f);
        for (int c = 0; c < 64; c++) g_w[4800 + c * 128 + t] = w2[t * 64 + c] * s2;
        g_w[12992 + t] = (b2[t] - m2[t]) * s2 + bt2[t];
    }
}

__global__ __launch_bounds__(512, 1) void fps_kernel(const float* __restrict__ xyz, float* __restrict__ nxyz) {
    extern __shared__ float sx[];            // 24576 floats
    __shared__ unsigned sval[2][32];         // [iter&1][warp] winner value bits (warps 16-31 unused: 0)
    __shared__ int      sidx[2][32];
    int b = blockIdx.x, t = threadIdx.x;
    int warp = t >> 5, lane = t & 31;
    if (t >= 16 && t < 32) {                 // neutral entries for nonexistent warps
        sval[0][t] = 0u; sidx[0][t] = 0x7fffffff;
        sval[1][t] = 0u; sidx[1][t] = 0x7fffffff;
    }
    const float4* src = (const float4*)(xyz + (size_t)b * NN * 3);
    float4* d4 = (float4*)sx;
    for (int i = t; i < 6144; i += 512) d4[i] = src[i];
    __syncthreads();
    // pair j holds points p0 = t + (2j)*512 (lo) and p1 = p0 + 512 (hi)
    u64 px2[8], py2[8], pz2[8];
    float dd[16];
#pragma unroll
    for (int j = 0; j < 8; j++) {
        int p0 = t + ((2 * j) << 9), p1 = p0 + 512;
        PK2(px2[j], sx[p0 * 3 + 0], sx[p1 * 3 + 0]);
        PK2(py2[j], sx[p0 * 3 + 1], sx[p1 * 3 + 1]);
        PK2(pz2[j], sx[p0 * 3 + 2], sx[p1 * 3 + 2]);
        dd[2 * j] = 1e10f; dd[2 * j + 1] = 1e10f;
    }
    int far = 0;
    float* ob = nxyz + (size_t)b * NS * 3;
    for (int it = 0; it < NS; it++) {
        float cx = sx[far * 3], cy = sx[far * 3 + 1], cz = sx[far * 3 + 2];
        if (t == 0) { ob[it * 3] = cx; ob[it * 3 + 1] = cy; ob[it * 3 + 2] = cz; }
        float ncx = -cx, ncy = -cy, ncz = -cz;
        u64 ncx2, ncy2, ncz2;
        PK2(ncx2, ncx, ncx); PK2(ncy2, ncy, ncy); PK2(ncz2, ncz, ncz);
        float m0 = -1.f, m1 = -1.f, m2 = -1.f, m3 = -1.f;
#pragma unroll
        for (int j = 0; j < 8; j++) {
            u64 dx, dy, dz, xx, yy, zz, s01;
            ADD2(dx, px2[j], ncx2);        // px - cx (exact: a + (-b) == a - b)
            ADD2(dy, py2[j], ncy2);
            ADD2(dz, pz2[j], ncz2);
            MUL2(xx, dx, dx);
            MUL2(yy, dy, dy);
            MUL2(zz, dz, dz);
            ADD2(s01, xx, yy);
            ADD2(s01, s01, zz);            // (x2+y2)+z2, same association as before
            float s0, s1;
            UPK2(s0, s1, s01);
            dd[2 * j]     = fminf(dd[2 * j], s0);
            dd[2 * j + 1] = fminf(dd[2 * j + 1], s1);
            float mj = fmaxf(dd[2 * j], dd[2 * j + 1]);
            if ((j & 3) == 0) m0 = fmaxf(m0, mj);
            else if ((j & 3) == 1) m1 = fmaxf(m1, mj);
            else if ((j & 3) == 2) m2 = fmaxf(m2, mj);
            else m3 = fmaxf(m3, mj);
        }
        float mymax = fmaxf(fmaxf(m0, m1), fmaxf(m2, m3));
        unsigned mb = __float_as_uint(mymax);          // nonneg floats: bit order == value order
        unsigned wmax = __reduce_max_sync(~0u, mb);
        unsigned p = 0x7fffffffu;
        if (mb == wmax) {
#pragma unroll
            for (int k = 15; k >= 0; k--)
                if (dd[k] == mymax) p = (unsigned)(t + (k << 9)); // descending k keeps smallest index
        }
        unsigned pw = __reduce_min_sync(~0u, p);
        if (lane == 0) { sval[it & 1][warp] = wmax; sidx[it & 1][warp] = (int)pw; }
        __syncthreads();
        // every warp reduces the same 32 (value, index) pairs; no atomics, no 2nd barrier
        unsigned v = sval[it & 1][lane];
        unsigned bm = __reduce_max_sync(~0u, v);
        unsigned cand = (v == bm) ? (unsigned)sidx[it & 1][lane] : 0x7fffffffu;
        far = (int)__reduce_min_sync(~0u, cand);
    }
}

__global__ __launch_bounds__(256) void ball_kernel(const float* __restrict__ xyz, const float* __restrict__ nxyz) {
    __shared__ float tile[6144];
    int b = blockIdx.x >> 8;
    int s = ((blockIdx.x & 255) << 3) + (threadIdx.x >> 5);
    int lane = threadIdx.x & 31;
    const float* nx = nxyz + (size_t)(b * NS + s) * 3;
    float cx = nx[0], cy = nx[1], cz = nx[2];
    float sn = cx * cx + cy * cy + cz * cz;
    const float R2 = 0.0625f, BIG = 1e30f;
    float kd = BIG; int ki = 0;
    float thr = BIG;
    for (int n0 = 0; n0 < NN; n0 += 2048) {
        __syncthreads();
        const float4* src = (const float4*)(xyz + (size_t)b * NN * 3 + n0 * 3);
        float4* d4 = (float4*)tile;
        for (int i = threadIdx.x; i < 1536; i += 256) d4[i] = src[i];
        __syncthreads();
        for (int c = 0; c < 2048; c += 32) {
            int p = c + lane;
            float x = tile[p * 3], y = tile[p * 3 + 1], z = tile[p * 3 + 2];
            float sp = x * x + y * y + z * z;
            float dot = x * cx + y * cy + z * cz;
            float d2 = sn + sp - 2.f * dot;
            unsigned m = __ballot_sync(~0u, d2 <= R2 && d2 < thr);
            while (m) {
                int sl = __ffs(m) - 1; m &= m - 1;
                float dv = __shfl_sync(~0u, d2, sl);
                if (dv < thr) {
                    // evict (max kd, tie: max ki, tie: max lane) -- same order as shfl version
                    unsigned kb = __float_as_uint(kd);
                    unsigned mx = __reduce_max_sync(~0u, kb);
                    unsigned cd = (kb == mx) ? (unsigned)ki : 0u;
                    unsigned mi = __reduce_max_sync(~0u, cd);
                    unsigned mk = __ballot_sync(~0u, (kb == mx) && ((unsigned)ki == mi));
                    int ml = 31 - __clz(mk);
                    if (lane == ml) { kd = dv; ki = n0 + c + sl; }
                    thr = __uint_as_float(__reduce_max_sync(~0u, __float_as_uint(kd)));
                }
            }
        }
    }
    float nv = kd; int ni = ki;
#pragma unroll
    for (int o = 16; o; o >>= 1) {
        float ov = __shfl_xor_sync(~0u, nv, o);
        int oi = __shfl_xor_sync(~0u, ni, o);
        if (ov < nv || (ov == nv && oi < ni)) { nv = ov; ni = oi; }
    }
    g_ball[((b * NS + s) << 5) + lane] = (kd >= BIG) ? ni : ki;
}

// SMEM: W[8448] | A0[2 pairs][64ch][64] | A1[same] = 24832 floats = 99328 B
// warp = (pair g = warp&1, cout-quarter h = warp>>1); lane = neighbor point.
// Each warp processes 2 samples per weight load. Activation layout [ch][lane*2+samp].
__global__ __launch_bounds__(256, 2) void mlp_kernel(const float* __restrict__ xyz, const float* __restrict__ pts,
                                                     const float* __restrict__ nxyz, float* __restrict__ outp) {
    extern __shared__ float S[];
    float* W  = S;
    float* A0 = S + 8448;
    float* A1 = S + 16640;
    int tid = threadIdx.x;
    int warp = tid >> 5, lane = tid & 31;
    int g = warp & 1, h = warp >> 1;
    int base = blockIdx.x * 4;
    int gsA = base + 2 * g, gsB = gsA + 1;   // two global sample indices for this warp
    {   // phase A: w0t,b0,w1t,b1 = 4800 floats
        const float4* g4 = (const float4*)g_w;
        float4* w4 = (float4*)W;
        for (int i = tid; i < 1200; i += 256) w4[i] = g4[i];
    }
    int bb = gsA >> 11;
    float fA[9], fB[9];
    {
        int gi = g_ball[(gsA << 5) + lane];
        const float* nx = nxyz + (size_t)gsA * 3;
        const float* P = xyz + (size_t)(bb * NN + gi) * 3;
        const float2* Q = (const float2*)(pts + (size_t)(bb * NN + gi) * 6);
        fA[0] = P[0] - nx[0]; fA[1] = P[1] - nx[1]; fA[2] = P[2] - nx[2];
        float2 q0 = Q[0], q1 = Q[1], q2 = Q[2];
        fA[3] = q0.x; fA[4] = q0.y; fA[5] = q1.x; fA[6] = q1.y; fA[7] = q2.x; fA[8] = q2.y;
    }
    {
        int gi = g_ball[(gsB << 5) + lane];
        const float* nx = nxyz + (size_t)gsB * 3;
        const float* P = xyz + (size_t)(bb * NN + gi) * 3;
        const float2* Q = (const float2*)(pts + (size_t)(bb * NN + gi) * 6);
        fB[0] = P[0] - nx[0]; fB[1] = P[1] - nx[1]; fB[2] = P[2] - nx[2];
        float2 q0 = Q[0], q1 = Q[1], q2 = Q[2];
        fB[3] = q0.x; fB[4] = q0.y; fB[5] = q1.x; fB[6] = q1.y; fB[7] = q2.x; fB[8] = q2.y;
    }
    __syncthreads();

    float* P0 = A0 + g * 4096;   // [64ch][64]: ch*64 + 2*lane + samp
    float* P1 = A1 + g * 4096;
    u64 acc[16];                 // acc[0..7] sample A (couts h*16+2q,+1), acc[8..15] sample B
    {   // layer1 9->64: couts [h*16, h*16+16)
        const u64* bp = (const u64*)(W + 576 + h * 16);
#pragma unroll
        for (int q = 0; q < 8; q++) { acc[q] = bp[q]; acc[8 + q] = bp[q]; }
#pragma unroll
        for (int c = 0; c < 9; c++) {
            u64 xa, xb; PK2(xa, fA[c], fA[c]); PK2(xb, fB[c], fB[c]);
            const ulonglong2* wr = (const ulonglong2*)(W + c * 64 + h * 16);
#pragma unroll
            for (int q = 0; q < 4; q++) {
                ulonglong2 w = wr[q];
                FMA2(acc[2 * q], xa, w.x, acc[2 * q]);
                FMA2(acc[2 * q + 1], xa, w.y, acc[2 * q + 1]);
                FMA2(acc[8 + 2 * q], xb, w.x, acc[8 + 2 * q]);
                FMA2(acc[9 + 2 * q], xb, w.y, acc[9 + 2 * q]);
            }
        }
#pragma unroll
        for (int q = 0; q < 8; q++) {
            float r0, r1, r2, r3;
            UPK2(r0, r1, acc[q]); UPK2(r2, r3, acc[8 + q]);
            int c0 = h * 16 + 2 * q;
            P0[c0 * 64 + 2 * lane]       = fmaxf(r0, 0.f);
            P0[(c0 + 1) * 64 + 2 * lane] = fmaxf(r1, 0.f);
            P0[c0 * 64 + 2 * lane + 1]       = fmaxf(r2, 0.f);
            P0[(c0 + 1) * 64 + 2 * lane + 1] = fmaxf(r3, 0.f);
        }
    }
    __syncthreads();
    {   // layer2 64->64
        const u64* bp = (const u64*)(W + 4736 + h * 16);
#pragma unroll
        for (int q = 0; q < 8; q++) { acc[q] = bp[q]; acc[8 + q] = bp[q]; }
#pragma unroll 8
        for (int c = 0; c < 64; c++) {
            float2 xv = *(const float2*)(P0 + c * 64 + 2 * lane);
            u64 xa, xb; PK2(xa, xv.x, xv.x); PK2(xb, xv.y, xv.y);
            const ulonglong2* wr = (const ulonglong2*)(W + 640 + c * 64 + h * 16);
#pragma unroll
            for (int q = 0; q < 4; q++) {
                ulonglong2 w = wr[q];
                FMA2(acc[2 * q], xa, w.x, acc[2 * q]);
                FMA2(acc[2 * q + 1], xa, w.y, acc[2 * q + 1]);
                FMA2(acc[8 + 2 * q], xb, w.x, acc[8 + 2 * q]);
                FMA2(acc[9 + 2 * q], xb, w.y, acc[9 + 2 * q]);
            }
        }
#pragma unroll
        for (int q = 0; q < 8; q++) {
            float r0, r1, r2, r3;
            UPK2(r0, r1, acc[q]); UPK2(r2, r3, acc[8 + q]);
            int c0 = h * 16 + 2 * q;
            P1[c0 * 64 + 2 * lane]       = fmaxf(r0, 0.f);
            P1[(c0 + 1) * 64 + 2 * lane] = fmaxf(r1, 0.f);
            P1[c0 * 64 + 2 * lane + 1]       = fmaxf(r2, 0.f);
            P1[(c0 + 1) * 64 + 2 * lane + 1] = fmaxf(r3, 0.f);
        }
    }
    __syncthreads();
    {   // phase B weights: w2t,b2 = 8320 floats
        const float4* g4 = (const float4*)(g_w + 4800);
        float4* w4 = (float4*)W;
        for (int i = tid; i < 2080; i += 256) w4[i] = g4[i];
    }
    __syncthreads();
#pragma unroll 1
    for (int sub = 0; sub < 2; sub++) {  // layer3 64->128: this warp covers couts [h*32, h*32+32) in 2 subs of 16
        int cb = h * 32 + sub * 16;
        const u64* bp = (const u64*)(W + 8192 + cb);
#pragma unroll
        for (int q = 0; q < 8; q++) { acc[q] = bp[q]; acc[8 + q] = bp[q]; }
#pragma unroll 8
        for (int c = 0; c < 64; c++) {
            float2 xv = *(const float2*)(P1 + c * 64 + 2 * lane);
            u64 xa, xb; PK2(xa, xv.x, xv.x); PK2(xb, xv.y, xv.y);
            const ulonglong2* wr = (const ulonglong2*)(W + c * 128 + cb);
#pragma unroll
            for (int q = 0; q < 4; q++) {
                ulonglong2 w = wr[q];
                FMA2(acc[2 * q], xa, w.x, acc[2 * q]);
                FMA2(acc[2 * q + 1], xa, w.y, acc[2 * q + 1]);
                FMA2(acc[8 + 2 * q], xb, w.x, acc[8 + 2 * q]);
                FMA2(acc[9 + 2 * q], xb, w.y, acc[9 + 2 * q]);
            }
        }
        // maxpool: 32 virtual couts = [sampleA couts 0..15, sampleB couts 0..15]
        float v[32];
#pragma unroll
        for (int q = 0; q < 8; q++) {
            UPK2(v[2 * q], v[2 * q + 1], acc[q]);
            UPK2(v[16 + 2 * q], v[17 + 2 * q], acc[8 + q]);
        }
#pragma unroll
        for (int o = 16; o; o >>= 1) {
#pragma unroll
            for (int j = 0; j < o; j++) {
                float xj   = (lane & o) ? v[j] : v[j + o];
                float r    = __shfl_xor_sync(~0u, xj, o);
                float mine = (lane & o) ? v[j + o] : v[j];
                v[j] = fmaxf(mine, r);
            }
        }
        if (lane < 16) outp[(size_t)gsA * 128 + cb + lane] = fmaxf(v[0], 0.f);
        else           outp[(size_t)gsB * 128 + cb + (lane - 16)] = fmaxf(v[0], 0.f);
    }
}

extern "C" void kernel_launch(void* const* d_in, const int* in_sizes, int n_in,
                              void* d_out, int out_size) {
    const float* xyz = (const float*)d_in[0];
    const float* pts = (const float*)d_in[1];
    float* out = (float*)d_out;
    float* nxyz = out;                       // (B,S,3)
    float* npts = out + NB * NS * 3;         // (B,S,128)
    cudaFuncSetAttribute(fps_kernel, cudaFuncAttributeMaxDynamicSharedMemorySize, 98304);
    cudaFuncSetAttribute(mlp_kernel, cudaFuncAttributeMaxDynamicSharedMemorySize, 99328);
    prep_kernel<<<1, 128>>>((const float*)d_in[2], (const float*)d_in[3], (const float*)d_in[4],
                            (const float*)d_in[5], (const float*)d_in[6], (const float*)d_in[7],
                            (const float*)d_in[8], (const float*)d_in[9], (const float*)d_in[10],
                            (const float*)d_in[11], (const float*)d_in[12], (const float*)d_in[13],
                            (const float*)d_in[14], (const float*)d_in[15], (const float*)d_in[16],
                            (const float*)d_in[17], (const float*)d_in[18], (const float*)d_in[19]);
    fps_kernel<<<NB, 512, 98304>>>(xyz, nxyz);
    ball_kernel<<<NB * 256, 256>>>(xyz, nxyz);
    mlp_kernel<<<NB * NS / 4, 256, 99328>>>(xyz, pts, nxyz, npts);
}

// round 11
// speedup vs baseline: 1.7320x; 1.2465x over previous
// Round 11: mega-kernel producer/consumer fusion — FPS blocks + ball/mlp worker queues
// overlap ball+mlp under the serial FPS phase. Arithmetic bit-identical to round 10.
#include <cuda_runtime.h>

#define NB 8
#define NN 8192
#define NS 2048

typedef unsigned long long u64;

#define PK2(d, lo, hi)   asm("mov.b64 %0, {%1,%2};" : "=l"(d) : "f"(lo), "f"(hi))
#define UPK2(lo, hi, v)  asm("mov.b64 {%0,%1}, %2;" : "=f"(lo), "=f"(hi) : "l"(v))
#define ADD2(d, a, b)    asm("add.rn.f32x2 %0, %1, %2;" : "=l"(d) : "l"(a), "l"(b))
#define MUL2(d, a, b)    asm("mul.rn.f32x2 %0, %1, %2;" : "=l"(d) : "l"(a), "l"(b))
#define FMA2(d, a, b, c) asm("fma.rn.f32x2 %0, %1, %2, %3;" : "=l"(d) : "l"(a), "l"(b), "l"(c))

// folded weights: w0t[9*64]@0 b0@576 w1t[64*64]@640 b1@4736 w2t[64*128]@4800 b2@12992
__device__ __align__(16) float g_w[13120];
__device__ int g_ball[NB * NS * 32];
__device__ volatile int g_prog[NB];     // fps progress (iterations complete) per batch
__device__ volatile int g_bf[1024];     // ball chunk done flags, idx k = window*8 + b
__device__ int g_bctr, g_mctr;          // work-queue counters

#define N_FPS   8
#define N_BALLW 32
#define GRID    152
#define SMEMB   183552                  // 45888 floats: W 13120 | A0 16384 | A1 16384

__global__ void prep_kernel(const float* w0, const float* b0, const float* g0, const float* bt0, const float* m0, const float* v0,
                            const float* w1, const float* b1, const float* g1, const float* bt1, const float* m1, const float* v1,
                            const float* w2, const float* b2, const float* g2, const float* bt2, const float* m2, const float* v2) {
    int t = threadIdx.x;
    for (int i = t; i < 1024; i += 128) g_bf[i] = 0;
    if (t < NB) g_prog[t] = 0;
    if (t == 0) { g_bctr = 0; g_mctr = 0; }
    if (t < 64) {
        float s = g0[t] * rsqrtf(v0[t] + 1e-5f);
        for (int c = 0; c < 9; c++) g_w[c * 64 + t] = w0[t * 9 + c] * s;
        g_w[576 + t] = (b0[t] - m0[t]) * s + bt0[t];
        float s1 = g1[t] * rsqrtf(v1[t] + 1e-5f);
        for (int c = 0; c < 64; c++) g_w[640 + c * 64 + t] = w1[t * 64 + c] * s1;
        g_w[4736 + t] = (b1[t] - m1[t]) * s1 + bt1[t];
    }
    if (t < 128) {
        float s2 = g2[t] * rsqrtf(v2[t] + 1e-5f);
        for (int c = 0; c < 64; c++) g_w[4800 + c * 128 + t] = w2[t * 64 + c] * s2;
        g_w[12992 + t] = (b2[t] - m2[t]) * s2 + bt2[t];
    }
}

__global__ __launch_bounds__(512) void mega_kernel(const float* __restrict__ xyz, const float* __restrict__ pts,
                                                   float* __restrict__ nxyz, float* __restrict__ outp) {
    extern __shared__ float S[];
    __shared__ int s_item;
    int tid = threadIdx.x, bid = blockIdx.x;
    int warp = tid >> 5, lane = tid & 31;

    if (bid < N_FPS) {
        // ---------------- FPS (identical arithmetic to round 10) ----------------
        float* sx = S;                                   // 24576 floats
        unsigned* sval = (unsigned*)(S + 24576);         // [2][32]
        int* sidx = (int*)(S + 24576 + 64);              // [2][32]
        int b = bid, t = tid;
        if (t >= 16 && t < 32) {
            sval[t] = 0u; sval[32 + t] = 0u;
            sidx[t] = 0x7fffffff; sidx[32 + t] = 0x7fffffff;
        }
        const float4* src = (const float4*)(xyz + (size_t)b * NN * 3);
        float4* d4 = (float4*)sx;
        for (int i = t; i < 6144; i += 512) d4[i] = src[i];
        __syncthreads();
        u64 px2[8], py2[8], pz2[8];
        float dd[16];
#pragma unroll
        for (int j = 0; j < 8; j++) {
            int p0 = t + ((2 * j) << 9), p1 = p0 + 512;
            PK2(px2[j], sx[p0 * 3 + 0], sx[p1 * 3 + 0]);
            PK2(py2[j], sx[p0 * 3 + 1], sx[p1 * 3 + 1]);
            PK2(pz2[j], sx[p0 * 3 + 2], sx[p1 * 3 + 2]);
            dd[2 * j] = 1e10f; dd[2 * j + 1] = 1e10f;
        }
        int far = 0;
        float* ob = nxyz + (size_t)b * NS * 3;
        for (int it = 0; it < NS; it++) {
            float cx = sx[far * 3], cy = sx[far * 3 + 1], cz = sx[far * 3 + 2];
            if (t == 0) {
                ob[it * 3] = cx; ob[it * 3 + 1] = cy; ob[it * 3 + 2] = cz;
                if ((it & 7) == 0 && it) { __threadfence(); g_prog[b] = it; }
            }
            float ncx = -cx, ncy = -cy, ncz = -cz;
            u64 ncx2, ncy2, ncz2;
            PK2(ncx2, ncx, ncx); PK2(ncy2, ncy, ncy); PK2(ncz2, ncz, ncz);
            float m0 = -1.f, m1 = -1.f, m2 = -1.f, m3 = -1.f;
#pragma unroll
            for (int j = 0; j < 8; j++) {
                u64 dx, dy, dz, xx, yy, zz, s01;
                ADD2(dx, px2[j], ncx2);
                ADD2(dy, py2[j], ncy2);
                ADD2(dz, pz2[j], ncz2);
                MUL2(xx, dx, dx);
                MUL2(yy, dy, dy);
                MUL2(zz, dz, dz);
                ADD2(s01, xx, yy);
                ADD2(s01, s01, zz);
                float s0, s1;
                UPK2(s0, s1, s01);
                dd[2 * j]     = fminf(dd[2 * j], s0);
                dd[2 * j + 1] = fminf(dd[2 * j + 1], s1);
                float mj = fmaxf(dd[2 * j], dd[2 * j + 1]);
                if ((j & 3) == 0) m0 = fmaxf(m0, mj);
                else if ((j & 3) == 1) m1 = fmaxf(m1, mj);
                else if ((j & 3) == 2) m2 = fmaxf(m2, mj);
                else m3 = fmaxf(m3, mj);
            }
            float mymax = fmaxf(fmaxf(m0, m1), fmaxf(m2, m3));
            unsigned mb = __float_as_uint(mymax);
            unsigned wmax = __reduce_max_sync(~0u, mb);
            unsigned p = 0x7fffffffu;
            if (mb == wmax) {
#pragma unroll
                for (int k = 15; k >= 0; k--)
                    if (dd[k] == mymax) p = (unsigned)(t + (k << 9));
            }
            unsigned pw = __reduce_min_sync(~0u, p);
            if (lane == 0) { sval[(it & 1) * 32 + warp] = wmax; sidx[(it & 1) * 32 + warp] = (int)pw; }
            __syncthreads();
            unsigned v = sval[(it & 1) * 32 + lane];
            unsigned bm = __reduce_max_sync(~0u, v);
            unsigned cand = (v == bm) ? (unsigned)sidx[(it & 1) * 32 + lane] : 0x7fffffffu;
            far = (int)__reduce_min_sync(~0u, cand);
        }
        if (t == 0) { __threadfence(); g_prog[b] = NS; }
        return;
    }

    // ---------------- ball workers (blocks 8..39) ----------------
    if (bid < N_FPS + N_BALLW) {
        const float R2 = 0.0625f, BIG = 1e30f;
        for (;;) {
            if (tid == 0) {
                int k = atomicAdd(&g_bctr, 1);
                s_item = k;
                if (k < 1024) {
                    int b = k & 7, s0 = (k >> 3) << 4;
                    while (g_prog[b] < s0 + 16) {}
                }
            }
            __syncthreads();
            int k = s_item;
            if (k >= 1024) break;
            int b = k & 7, s0 = (k >> 3) << 4;
            // stage whole batch xyz
            const float4* src = (const float4*)(xyz + (size_t)b * NN * 3);
            float4* d4 = (float4*)S;
            for (int i = tid; i < 6144; i += 512) d4[i] = src[i];
            __syncthreads();
            int s = s0 + warp;
            const float* nx = nxyz + (size_t)(b * NS + s) * 3;
            float cx = nx[0], cy = nx[1], cz = nx[2];
            float sn = cx * cx + cy * cy + cz * cz;
            float kd = BIG; int ki = 0;
            float thr = BIG;
            for (int c = 0; c < NN; c += 32) {
                int p = c + lane;
                float x = S[p * 3], y = S[p * 3 + 1], z = S[p * 3 + 2];
                float sp = x * x + y * y + z * z;
                float dot = x * cx + y * cy + z * cz;
                float d2 = sn + sp - 2.f * dot;
                unsigned m = __ballot_sync(~0u, d2 <= R2 && d2 < thr);
                while (m) {
                    int sl = __ffs(m) - 1; m &= m - 1;
                    float dv = __shfl_sync(~0u, d2, sl);
                    if (dv < thr) {
                        unsigned kb = __float_as_uint(kd);
                        unsigned mx = __reduce_max_sync(~0u, kb);
                        unsigned cd = (kb == mx) ? (unsigned)ki : 0u;
                        unsigned mi = __reduce_max_sync(~0u, cd);
                        unsigned mk = __ballot_sync(~0u, (kb == mx) && ((unsigned)ki == mi));
                        int ml = 31 - __clz(mk);
                        if (lane == ml) { kd = dv; ki = c + sl; }
                        thr = __uint_as_float(__reduce_max_sync(~0u, __float_as_uint(kd)));
                    }
                }
            }
            float nv = kd; int ni = ki;
#pragma unroll
            for (int o = 16; o; o >>= 1) {
                float ov = __shfl_xor_sync(~0u, nv, o);
                int oi = __shfl_xor_sync(~0u, ni, o);
                if (ov < nv || (ov == nv && oi < ni)) { nv = ov; ni = oi; }
            }
            g_ball[((b * NS + s) << 5) + lane] = (kd >= BIG) ? ni : ki;
            __threadfence();
            __syncthreads();
            if (tid == 0) g_bf[k] = 1;
        }
        __syncthreads();
    }

    // ---------------- mlp workers (ball workers join after draining) ----------------
    {   // load full folded weights once per persistent block
        const float4* g4 = (const float4*)g_w;
        float4* w4 = (float4*)S;
        for (int i = tid; i < 3280; i += 512) w4[i] = g4[i];
    }
    __syncthreads();
    float* W  = S;
    float* A0 = S + 13120;
    float* A1 = S + 29504;
    int g = warp & 3, h = warp >> 2;
    for (;;) {
        if (tid == 0) {
            int m = atomicAdd(&g_mctr, 1);
            s_item = m;
            if (m < 2048) {
                int b = m & 7, w2 = m >> 3;
                int kneed = ((w2 >> 1) << 3) + b;
                while (g_bf[kneed] == 0) {}
            }
        }
        __syncthreads();
        int m = s_item;
        if (m >= 2048) break;
        int b = m & 7, w2 = m >> 3;
        int base = b * NS + w2 * 8;
        int gsA = base + 2 * g, gsB = gsA + 1;
        float fA[9], fB[9];
        {
            int gi = g_ball[(gsA << 5) + lane];
            const float* nx = nxyz + (size_t)gsA * 3;
            const float* P = xyz + (size_t)(b * NN + gi) * 3;
            const float2* Q = (const float2*)(pts + (size_t)(b * NN + gi) * 6);
            fA[0] = P[0] - nx[0]; fA[1] = P[1] - nx[1]; fA[2] = P[2] - nx[2];
            float2 q0 = Q[0], q1 = Q[1], q2 = Q[2];
            fA[3] = q0.x; fA[4] = q0.y; fA[5] = q1.x; fA[6] = q1.y; fA[7] = q2.x; fA[8] = q2.y;
        }
        {
            int gi = g_ball[(gsB << 5) + lane];
            const float* nx = nxyz + (size_t)gsB * 3;
            const float* P = xyz + (size_t)(b * NN + gi) * 3;
            const float2* Q = (const float2*)(pts + (size_t)(b * NN + gi) * 6);
            fB[0] = P[0] - nx[0]; fB[1] = P[1] - nx[1]; fB[2] = P[2] - nx[2];
            float2 q0 = Q[0], q1 = Q[1], q2 = Q[2];
            fB[3] = q0.x; fB[4] = q0.y; fB[5] = q1.x; fB[6] = q1.y; fB[7] = q2.x; fB[8] = q2.y;
        }
        float* P0 = A0 + g * 4096;   // [64ch][64]: ch*64 + 2*lane + samp
        float* P1 = A1 + g * 4096;
        u64 acc[16];
        {   // layer1 9->64: couts [h*16, h*16+16)
            const u64* bp = (const u64*)(W + 576 + h * 16);
#pragma unroll
            for (int q = 0; q < 8; q++) { acc[q] = bp[q]; acc[8 + q] = bp[q]; }
#pragma unroll
            for (int c = 0; c < 9; c++) {
                u64 xa, xb; PK2(xa, fA[c], fA[c]); PK2(xb, fB[c], fB[c]);
                const ulonglong2* wr = (const ulonglong2*)(W + c * 64 + h * 16);
#pragma unroll
                for (int q = 0; q < 4; q++) {
                    ulonglong2 w = wr[q];
                    FMA2(acc[2 * q], xa, w.x, acc[2 * q]);
                    FMA2(acc[2 * q + 1], xa, w.y, acc[2 * q + 1]);
                    FMA2(acc[8 + 2 * q], xb, w.x, acc[8 + 2 * q]);
                    FMA2(acc[9 + 2 * q], xb, w.y, acc[9 + 2 * q]);
                }
            }
#pragma unroll
            for (int q = 0; q < 8; q++) {
                float r0, r1, r2, r3;
                UPK2(r0, r1, acc[q]); UPK2(r2, r3, acc[8 + q]);
                int c0 = h * 16 + 2 * q;
                P0[c0 * 64 + 2 * lane]           = fmaxf(r0, 0.f);
                P0[(c0 + 1) * 64 + 2 * lane]     = fmaxf(r1, 0.f);
                P0[c0 * 64 + 2 * lane + 1]       = fmaxf(r2, 0.f);
                P0[(c0 + 1) * 64 + 2 * lane + 1] = fmaxf(r3, 0.f);
            }
        }
        __syncthreads();
        {   // layer2 64->64
            const u64* bp = (const u64*)(W + 4736 + h * 16);
#pragma unroll
            for (int q = 0; q < 8; q++) { acc[q] = bp[q]; acc[8 + q] = bp[q]; }
#pragma unroll 8
            for (int c = 0; c < 64; c++) {
                float2 xv = *(const float2*)(P0 + c * 64 + 2 * lane);
                u64 xa, xb; PK2(xa, xv.x, xv.x); PK2(xb, xv.y, xv.y);
                const ulonglong2* wr = (const ulonglong2*)(W + 640 + c * 64 + h * 16);
#pragma unroll
                for (int q = 0; q < 4; q++) {
                    ulonglong2 w = wr[q];
                    FMA2(acc[2 * q], xa, w.x, acc[2 * q]);
                    FMA2(acc[2 * q + 1], xa, w.y, acc[2 * q + 1]);
                    FMA2(acc[8 + 2 * q], xb, w.x, acc[8 + 2 * q]);
                    FMA2(acc[9 + 2 * q], xb, w.y, acc[9 + 2 * q]);
                }
            }
#pragma unroll
            for (int q = 0; q < 8; q++) {
                float r0, r1, r2, r3;
                UPK2(r0, r1, acc[q]); UPK2(r2, r3, acc[8 + q]);
                int c0 = h * 16 + 2 * q;
                P1[c0 * 64 + 2 * lane]           = fmaxf(r0, 0.f);
                P1[(c0 + 1) * 64 + 2 * lane]     = fmaxf(r1, 0.f);
                P1[c0 * 64 + 2 * lane + 1]       = fmaxf(r2, 0.f);
                P1[(c0 + 1) * 64 + 2 * lane + 1] = fmaxf(r3, 0.f);
            }
        }
        __syncthreads();
#pragma unroll 1
        for (int sub = 0; sub < 2; sub++) {  // layer3 64->128: couts [h*32, h*32+32) in 2 subs of 16
            int cb = h * 32 + sub * 16;
            const u64* bp = (const u64*)(W + 12992 + cb);
#pragma unroll
            for (int q = 0; q < 8; q++) { acc[q] = bp[q]; acc[8 + q] = bp[q]; }
#pragma unroll 8
            for (int c = 0; c < 64; c++) {
                float2 xv = *(const float2*)(P1 + c * 64 + 2 * lane);
                u64 xa, xb; PK2(xa, xv.x, xv.x); PK2(xb, xv.y, xv.y);
                const ulonglong2* wr = (const ulonglong2*)(W + 4800 + c * 128 + cb);
#pragma unroll
                for (int q = 0; q < 4; q++) {
                    ulonglong2 w = wr[q];
                    FMA2(acc[2 * q], xa, w.x, acc[2 * q]);
                    FMA2(acc[2 * q + 1], xa, w.y, acc[2 * q + 1]);
                    FMA2(acc[8 + 2 * q], xb, w.x, acc[8 + 2 * q]);
                    FMA2(acc[9 + 2 * q], xb, w.y, acc[9 + 2 * q]);
                }
            }
            float v[32];
#pragma unroll
            for (int q = 0; q < 8; q++) {
                UPK2(v[2 * q], v[2 * q + 1], acc[q]);
                UPK2(v[16 + 2 * q], v[17 + 2 * q], acc[8 + q]);
            }
#pragma unroll
            for (int o = 16; o; o >>= 1) {
#pragma unroll
                for (int j = 0; j < o; j++) {
                    float xj   = (lane & o) ? v[j] : v[j + o];
                    float r    = __shfl_xor_sync(~0u, xj, o);
                    float mine = (lane & o) ? v[j + o] : v[j];
                    v[j] = fmaxf(mine, r);
                }
            }
            if (lane < 16) outp[(size_t)gsA * 128 + cb + lane] = fmaxf(v[0], 0.f);
            else           outp[(size_t)gsB * 128 + cb + (lane - 16)] = fmaxf(v[0], 0.f);
        }
    }
}

extern "C" void kernel_launch(void* const* d_in, const int* in_sizes, int n_in,
                              void* d_out, int out_size) {
    const float* xyz = (const float*)d_in[0];
    const float* pts = (const float*)d_in[1];
    float* out = (float*)d_out;
    float* nxyz = out;                       // (B,S,3)
    float* npts = out + NB * NS * 3;         // (B,S,128)
    cudaFuncSetAttribute(mega_kernel, cudaFuncAttributeMaxDynamicSharedMemorySize, SMEMB);
    prep_kernel<<<1, 128>>>((const float*)d_in[2], (const float*)d_in[3], (const float*)d_in[4],
                            (const float*)d_in[5], (const float*)d_in[6], (const float*)d_in[7],
                            (const float*)d_in[8], (const float*)d_in[9], (const float*)d_in[10],
                            (const float*)d_in[11], (const float*)d_in[12], (const float*)d_in[13],
                            (const float*)d_in[14], (const float*)d_in[15], (const float*)d_in[16],
                            (const float*)d_in[17], (const float*)d_in[18], (const float*)d_in[19]);
    mega_kernel<<<GRID, 512, SMEMB>>>(xyz, pts, nxyz, npts);
}